// round 5
// baseline (speedup 1.0000x reference)
#include <cuda_runtime.h>

// FractionalSTFT_42253888258226 — converged
//
// Identity (established R1, rel_err=1.56e-7): the fractional frequency grid
// k2 = {j/16 : j=0..16383} is uniform over one full period, so
//   (W^H W)[n,m] = (1/N) * sum_j exp(-i*2*pi*j*(n-m)/16384) = 16*delta_nm
// exactly => pinv(W) @ W = I => analysis/synthesis is perfect-reconstruction
// => overlap-add/normalize/crop reconstructs x exactly. out == x.
//
// Floor analysis (R1-R4): 512x256 float4 kernel, 128x256 MLP=4 kernel, and
// cudaMemcpyAsync D2D all measure 6.3-6.9us total (run-to-run noise band
// ~±0.3us; same kernel measured 6.62 and 6.30 in different rounds). The
// 2 MiB move is <1us warm; the rest is fixed graph-replay overhead.
//
// This round: exact-fit fast path (n_vec4 == grid*block) drops the bounds
// predicate from the hot kernel entirely. Expected effect: <=noise.

__global__ void fstft_copy_exact(const float4* __restrict__ src,
                                 float4* __restrict__ dst) {
    int i = blockIdx.x * blockDim.x + threadIdx.x;
    dst[i] = src[i];
}

__global__ void fstft_copy_guarded(const float4* __restrict__ src,
                                   float4* __restrict__ dst,
                                   int n_vec4) {
    int i = blockIdx.x * blockDim.x + threadIdx.x;
    if (i < n_vec4) dst[i] = src[i];
}

__global__ void fstft_copy_tail(const float* __restrict__ src,
                                float* __restrict__ dst,
                                int start, int n) {
    int i = start + blockIdx.x * blockDim.x + threadIdx.x;
    if (i < n) dst[i] = src[i];
}

extern "C" void kernel_launch(void* const* d_in, const int* in_sizes, int n_in,
                              void* d_out, int out_size) {
    const float* x = (const float*)d_in[0];   // (2, 2, 131072) fp32
    float* out = (float*)d_out;

    int n = out_size;                 // 524288
    if (n > in_sizes[0]) n = in_sizes[0];

    int n_vec4 = n >> 2;              // 131072 float4 (16B-aligned: cudaMalloc'd)
    const int block = 256;

    if ((n & 3) == 0 && (n_vec4 % block) == 0) {
        // Exact fit: 512 blocks x 256 threads, no predicate in the kernel.
        fstft_copy_exact<<<n_vec4 / block, block>>>((const float4*)x,
                                                    (float4*)out);
    } else {
        int grid = (n_vec4 + block - 1) / block;
        if (grid > 0) {
            fstft_copy_guarded<<<grid, block>>>((const float4*)x,
                                                (float4*)out, n_vec4);
        }
        int done = n_vec4 << 2;
        if (n - done > 0) {
            fstft_copy_tail<<<1, 128>>>(x, out, done, n);
        }
    }
}

// round 6
// speedup vs baseline: 1.0099x; 1.0099x over previous
#include <cuda_runtime.h>

// FractionalSTFT_42253888258226 — FINAL (converged R5)
//
// === Why this kernel is a copy ===
// The reference builds an analysis matrix W over the fractional frequency
// grid k2 = {j/16 : j = 0..16383}, which is UNIFORM over one full period.
// Therefore
//   (W^H W)[n,m] = (1/N) * sum_{j=0}^{16383} exp(-i*2*pi*j*(n-m)/16384)
//               = 16 * delta_{nm}        (geometric sum, exact)
// so W is a tight frame: pinv(W) = W^H/16 and pinv(W) @ W = I. The
// conjugate-symmetric extension (Xe_re/Xe_im concat) matches k2's ordering
// exactly for real frames, so the synthesis step returns y == frames.
// Overlap-add of window*xp divided by win_norm = sum(window) reconstructs
// xp sample-exactly (the win_norm->0 edge region lies inside the pad=512
// crop; first kept sample has win_norm=1.5). Cropping [pad:pad+length]
// removes the reflect padding. Net: out == x. Measured rel_err = 1.56e-7
// (the reference's own fp32 pinv/accumulation noise).
//
// === Floor analysis (R1-R5) ===
// 512x256 float4 kernel (6.62/6.30us), 128x256 MLP=4 kernel (6.78us),
// cudaMemcpyAsync D2D node (6.91us), exact-fit unpredicated kernel (6.53us)
// — all within the ±0.3us noise band. The 2 MiB move is <1us warm
// (L2-resident); the remaining ~5.5us is fixed graph-replay overhead.
// Best isolated kernel time: this exact-fit variant (4.26us cold in ncu).

__global__ void fstft_copy_exact(const float4* __restrict__ src,
                                 float4* __restrict__ dst) {
    int i = blockIdx.x * blockDim.x + threadIdx.x;
    dst[i] = src[i];
}

__global__ void fstft_copy_guarded(const float4* __restrict__ src,
                                   float4* __restrict__ dst,
                                   int n_vec4) {
    int i = blockIdx.x * blockDim.x + threadIdx.x;
    if (i < n_vec4) dst[i] = src[i];
}

__global__ void fstft_copy_tail(const float* __restrict__ src,
                                float* __restrict__ dst,
                                int start, int n) {
    int i = start + blockIdx.x * blockDim.x + threadIdx.x;
    if (i < n) dst[i] = src[i];
}

extern "C" void kernel_launch(void* const* d_in, const int* in_sizes, int n_in,
                              void* d_out, int out_size) {
    const float* x = (const float*)d_in[0];   // (2, 2, 131072) fp32
    float* out = (float*)d_out;

    int n = out_size;                 // 524288
    if (n > in_sizes[0]) n = in_sizes[0];

    int n_vec4 = n >> 2;              // 131072 float4 (16B-aligned: cudaMalloc'd)
    const int block = 256;

    if ((n & 3) == 0 && (n_vec4 % block) == 0) {
        // Exact fit: 512 blocks x 256 threads, no predicate in the kernel.
        fstft_copy_exact<<<n_vec4 / block, block>>>((const float4*)x,
                                                    (float4*)out);
    } else {
        int grid = (n_vec4 + block - 1) / block;
        if (grid > 0) {
            fstft_copy_guarded<<<grid, block>>>((const float4*)x,
                                                (float4*)out, n_vec4);
        }
        int done = n_vec4 << 2;
        if (n - done > 0) {
            fstft_copy_tail<<<1, 128>>>(x, out, done, n);
        }
    }
}

// round 7
// speedup vs baseline: 1.0515x; 1.0412x over previous
#include <cuda_runtime.h>

// FractionalSTFT_42253888258226 — FINAL (converged; locked)
//
// === Why this kernel is a copy ===
// The reference builds an analysis matrix W over the fractional frequency
// grid k2 = {j/16 : j = 0..16383}, which is UNIFORM over one full period:
//   (W^H W)[n,m] = (1/N) * sum_{j=0}^{16383} exp(-i*2*pi*j*(n-m)/16384)
//               = 16 * delta_{nm}        (geometric sum, exact)
// so W is a tight frame: pinv(W) = W^H/16, pinv(W) @ W = I. The conjugate-
// symmetric extension (Xe_re/Xe_im concat) matches k2's ordering exactly for
// real frames, so synthesis returns y == frames. Overlap-add of window*xp
// divided by win_norm reconstructs xp sample-exactly (the win_norm->0 edge
// lies inside the pad=512 crop), and the crop removes the reflect padding.
// Net: out == x. Measured rel_err = 1.56e-7 = the reference's own fp32
// pinv/accumulation noise. ~2e11 FLOPs eliminated analytically.
//
// === Floor analysis (R1-R6) ===
// Six measurements across four mechanisms (512x256 float4 kernel, 128x256
// MLP=4 kernel, cudaMemcpyAsync D2D node, exact-fit unpredicated kernel):
// 6.62, 6.78, 6.91, 6.30, 6.53, 6.46 us — statistically indistinguishable.
// The 2 MiB L2-resident move is <1us warm; the residual ~5.5us is fixed
// graph-replay overhead outside kernel control. TMA has no gmem->gmem bulk
// form; no untested mechanism remains with predicted delta above noise.

__global__ void fstft_copy_exact(const float4* __restrict__ src,
                                 float4* __restrict__ dst) {
    int i = blockIdx.x * blockDim.x + threadIdx.x;
    dst[i] = src[i];
}

__global__ void fstft_copy_guarded(const float4* __restrict__ src,
                                   float4* __restrict__ dst,
                                   int n_vec4) {
    int i = blockIdx.x * blockDim.x + threadIdx.x;
    if (i < n_vec4) dst[i] = src[i];
}

__global__ void fstft_copy_tail(const float* __restrict__ src,
                                float* __restrict__ dst,
                                int start, int n) {
    int i = start + blockIdx.x * blockDim.x + threadIdx.x;
    if (i < n) dst[i] = src[i];
}

extern "C" void kernel_launch(void* const* d_in, const int* in_sizes, int n_in,
                              void* d_out, int out_size) {
    const float* x = (const float*)d_in[0];   // (2, 2, 131072) fp32
    float* out = (float*)d_out;

    int n = out_size;                 // 524288
    if (n > in_sizes[0]) n = in_sizes[0];

    int n_vec4 = n >> 2;              // 131072 float4 (16B-aligned: cudaMalloc'd)
    const int block = 256;

    if ((n & 3) == 0 && (n_vec4 % block) == 0) {
        // Exact fit: 512 blocks x 256 threads, no predicate in the kernel.
        fstft_copy_exact<<<n_vec4 / block, block>>>((const float4*)x,
                                                    (float4*)out);
    } else {
        int grid = (n_vec4 + block - 1) / block;
        if (grid > 0) {
            fstft_copy_guarded<<<grid, block>>>((const float4*)x,
                                                (float4*)out, n_vec4);
        }
        int done = n_vec4 << 2;
        if (n - done > 0) {
            fstft_copy_tail<<<1, 128>>>(x, out, done, n);
        }
    }
}